// round 3
// baseline (speedup 1.0000x reference)
#include <cuda_runtime.h>
#include <math.h>

#define B 512
#define V 6890
#define NJ 24
#define D3 (V*3)              /* 20670 */
#define D3PAD 20672
#define KF 108
#define OFF_V 0
#define OFF_POSED (B*D3)
#define OFF_SHAPED (2*B*D3)
#define OFF_J (3*B*D3)

__constant__ int c_parent[23] = {0,0,0,1,2,3,4,5,6,7,8,9,9,9,12,13,14,16,17,18,19,20,21};

// scratch (static device globals; no allocation)
__device__ float g_F[B*KF];            // packed feature rows [betas(10),0,0,quat[4:96],betas[1],0,0,0]
__device__ float g_Dcomb[D3PAD*KF];    // packed dirs rows, zero-padded
__device__ float g_quat[B*NJ*4];       // [s*n, c-1]
__device__ float g_R[B*NJ*9];
__device__ float g_Jp[B*NJ*3];
__device__ float g_Gskin[B*NJ*12];

// ---------------- pack dirs ----------------
__global__ void k_dirs(const float* __restrict__ shapedirs,
                       const float* __restrict__ posedirs) {
    int idx = blockIdx.x * 256 + threadIdx.x;
    if (idx >= D3PAD * KF) return;
    int row = idx / KF;
    int col = idx - row * KF;
    float v = 0.f;
    if (row < D3) {
        if (col < 10)                  v = shapedirs[row * 10 + col];
        else if (col >= 12 && col < 105) v = posedirs[row * 93 + (col - 12)];
    }
    g_Dcomb[idx] = v;
}

// ---------------- quaternion + rodrigues ----------------
__global__ void k_rot(const float* __restrict__ pose) {
    int i = blockIdx.x * 128 + threadIdx.x;
    if (i >= B * NJ) return;
    float tx = pose[i*3+0], ty = pose[i*3+1], tz = pose[i*3+2];
    float ax = tx + 1e-8f, ay = ty + 1e-8f, az = tz + 1e-8f;
    float angle = sqrtf(ax*ax + ay*ay + az*az);
    float inv = 1.0f / angle;
    float nx = tx*inv, ny = ty*inv, nz = tz*inv;
    float half = 0.5f * angle;
    float c = cosf(half), s = sinf(half);
    float x = s*nx, y = s*ny, z = s*nz, w = c;
    g_quat[i*4+0] = x; g_quat[i*4+1] = y; g_quat[i*4+2] = z; g_quat[i*4+3] = c - 1.0f;
    float xx=x*x, yy=y*y, zz=z*z;
    float wx=w*x, wy=w*y, wz=w*z;
    float xy=x*y, xz=x*z, yz=y*z;
    float* R = &g_R[i*9];
    R[0]=1.f-2.f*(yy+zz); R[1]=2.f*(xy-wz);      R[2]=2.f*(xz+wy);
    R[3]=2.f*(xy+wz);     R[4]=1.f-2.f*(xx+zz);  R[5]=2.f*(yz-wx);
    R[6]=2.f*(xz-wy);     R[7]=2.f*(yz+wx);      R[8]=1.f-2.f*(xx+yy);
}

// ---------------- pack features ----------------
__global__ void k_feat(const float* __restrict__ betas) {
    int idx = blockIdx.x * 256 + threadIdx.x;
    if (idx >= B * KF) return;
    int b = idx / KF;
    int k = idx - b * KF;
    float v = 0.f;
    if (k < 10)                     v = betas[b*10 + k];
    else if (k >= 12 && k < 104)    v = g_quat[b*96 + 4 + (k - 12)];
    else if (k == 104)              v = betas[b*10 + 1];
    g_F[idx] = v;
}

// ---------------- fused blendshape GEMM: v_shaped + v_posed ----------------
// out[b,d]_posed  = dot(Dcomb[d,0:108], F[b,0:108]) + v_template[d]
// out[b,d]_shaped = dot(Dcomb[d,0:12],  F[b,0:12])  + v_template[d]   (snapshot)
__global__ void __launch_bounds__(256) k_gemm(const float* __restrict__ v_template,
                                              float* __restrict__ out) {
    extern __shared__ float sm[];
    float* Ds = sm;               // 64 x 108
    float* Fs = sm + 64 * KF;     // 64 x 108
    int dtile = blockIdx.x * 64;
    int btile = blockIdx.y * 64;
    int tx = threadIdx.x, ty = threadIdx.y;
    int tid = ty * 16 + tx;

    // rows beyond D3 in g_Dcomb are zero-filled -> no guard needed
    #pragma unroll
    for (int i = tid; i < 64 * KF; i += 256) Ds[i] = g_Dcomb[dtile * KF + i];
    #pragma unroll
    for (int i = tid; i < 64 * KF; i += 256) Fs[i] = g_F[btile * KF + i];
    __syncthreads();

    float acc[4][4], accS[4][4];
    #pragma unroll
    for (int i = 0; i < 4; i++)
        #pragma unroll
        for (int j = 0; j < 4; j++) { acc[i][j] = 0.f; accS[i][j] = 0.f; }

    #pragma unroll
    for (int kq = 0; kq < 27; ++kq) {
        float4 dv[4], fv[4];
        #pragma unroll
        for (int i = 0; i < 4; i++)
            dv[i] = *(const float4*)&Ds[(tx + i*16) * KF + kq*4];
        #pragma unroll
        for (int j = 0; j < 4; j++)
            fv[j] = *(const float4*)&Fs[(ty + j*16) * KF + kq*4];
        #pragma unroll
        for (int i = 0; i < 4; i++)
            #pragma unroll
            for (int j = 0; j < 4; j++) {
                float a = acc[i][j];
                a = fmaf(dv[i].x, fv[j].x, a);
                a = fmaf(dv[i].y, fv[j].y, a);
                a = fmaf(dv[i].z, fv[j].z, a);
                a = fmaf(dv[i].w, fv[j].w, a);
                acc[i][j] = a;
            }
        if (kq == 2) {
            #pragma unroll
            for (int i = 0; i < 4; i++)
                #pragma unroll
                for (int j = 0; j < 4; j++) accS[i][j] = acc[i][j];
        }
    }

    #pragma unroll
    for (int i = 0; i < 4; i++) {
        int d = dtile + tx + i*16;
        if (d >= D3) continue;
        float vt = v_template[d];
        #pragma unroll
        for (int j = 0; j < 4; j++) {
            int b = btile + ty + j*16;
            out[OFF_POSED  + b * D3 + d] = acc[i][j]  + vt;
            out[OFF_SHAPED + b * D3 + d] = accS[i][j] + vt;
        }
    }
}

// ---------------- Jp = J_regressor @ v_shaped ----------------
__global__ void __launch_bounds__(256) k_joints(const float* __restrict__ out,
                                                const float* __restrict__ Jr) {
    int b = blockIdx.x;
    const float* vs = out + OFF_SHAPED + b * D3;
    float acc[72];
    #pragma unroll
    for (int k = 0; k < 72; k++) acc[k] = 0.f;

    for (int v = threadIdx.x; v < V; v += 256) {
        float x = vs[v*3+0], y = vs[v*3+1], z = vs[v*3+2];
        #pragma unroll
        for (int j = 0; j < NJ; j++) {
            float w = __ldg(&Jr[j * V + v]);
            acc[j*3+0] += w * x;
            acc[j*3+1] += w * y;
            acc[j*3+2] += w * z;
        }
    }

    __shared__ float red[8][72];
    int lane = threadIdx.x & 31, wid = threadIdx.x >> 5;
    #pragma unroll
    for (int k = 0; k < 72; k++) {
        float s = acc[k];
        s += __shfl_down_sync(0xffffffffu, s, 16);
        s += __shfl_down_sync(0xffffffffu, s, 8);
        s += __shfl_down_sync(0xffffffffu, s, 4);
        s += __shfl_down_sync(0xffffffffu, s, 2);
        s += __shfl_down_sync(0xffffffffu, s, 1);
        if (lane == 0) red[wid][k] = s;
    }
    __syncthreads();
    if (threadIdx.x < 72) {
        float s = 0.f;
        #pragma unroll
        for (int w2 = 0; w2 < 8; w2++) s += red[w2][threadIdx.x];
        g_Jp[b * 72 + threadIdx.x] = s;
    }
}

// ---------------- kinematic chain (1 thread per batch) ----------------
__global__ void k_chain(const float* __restrict__ trans, float* __restrict__ out) {
    int b = blockIdx.x * 64 + threadIdx.x;
    if (b >= B) return;

    float jp[NJ][3];
    #pragma unroll
    for (int j = 0; j < NJ; j++) {
        jp[j][0] = g_Jp[b*72 + j*3 + 0];
        jp[j][1] = g_Jp[b*72 + j*3 + 1];
        jp[j][2] = g_Jp[b*72 + j*3 + 2];
    }

    float G[NJ][12];   // 3x4, row-major
    {
        const float* R = &g_R[(b*NJ + 0) * 9];
        G[0][0]=R[0]; G[0][1]=R[1]; G[0][2]=R[2];  G[0][3]=jp[0][0];
        G[0][4]=R[3]; G[0][5]=R[4]; G[0][6]=R[5];  G[0][7]=jp[0][1];
        G[0][8]=R[6]; G[0][9]=R[7]; G[0][10]=R[8]; G[0][11]=jp[0][2];
    }
    for (int i = 1; i < NJ; i++) {
        int p = c_parent[i-1];
        const float* R = &g_R[(b*NJ + i) * 9];
        float t0 = jp[i][0] - jp[p][0];
        float t1 = jp[i][1] - jp[p][1];
        float t2 = jp[i][2] - jp[p][2];
        const float* Gp = G[p];
        float* Gi = G[i];
        #pragma unroll
        for (int r = 0; r < 3; r++) {
            float a0 = Gp[r*4+0], a1 = Gp[r*4+1], a2 = Gp[r*4+2];
            Gi[r*4+0] = a0*R[0] + a1*R[3] + a2*R[6];
            Gi[r*4+1] = a0*R[1] + a1*R[4] + a2*R[7];
            Gi[r*4+2] = a0*R[2] + a1*R[5] + a2*R[8];
            Gi[r*4+3] = a0*t0 + a1*t1 + a2*t2 + Gp[r*4+3];
        }
    }

    float trx = trans[b*3+0], try_ = trans[b*3+1], trz = trans[b*3+2];
    for (int j = 0; j < NJ; j++) {
        out[OFF_J + b*72 + j*3 + 0] = G[j][3]  + trx;
        out[OFF_J + b*72 + j*3 + 1] = G[j][7]  + try_;
        out[OFF_J + b*72 + j*3 + 2] = G[j][11] + trz;
        float px = jp[j][0], py = jp[j][1], pz = jp[j][2];
        float* Gs = &g_Gskin[(b*NJ + j) * 12];
        #pragma unroll
        for (int r = 0; r < 3; r++) {
            float r0 = G[j][r*4+0], r1 = G[j][r*4+1], r2 = G[j][r*4+2];
            Gs[r*4+0] = r0; Gs[r*4+1] = r1; Gs[r*4+2] = r2;
            Gs[r*4+3] = G[j][r*4+3] - (r0*px + r1*py + r2*pz);
        }
    }
}

// ---------------- LBS skinning ----------------
__global__ void __launch_bounds__(256) k_skin(const float* __restrict__ weights,
                                              const float* __restrict__ trans,
                                              float* __restrict__ out) {
    int b = blockIdx.y;
    __shared__ float Gs[NJ * 12];   // 288 floats
    __shared__ float tr[3];
    int tid = threadIdx.x;
    // FIX: 288 > 256 threads — strided load (previous round left Gs[256..287]
    // uninitialized, dropping joints >= 21 from the blend -> rel_err 0.107)
    for (int i = tid; i < NJ * 12; i += 256) Gs[i] = g_Gskin[b * NJ * 12 + i];
    if (tid < 3) tr[tid] = trans[b*3 + tid];
    __syncthreads();

    int v = blockIdx.x * 256 + tid;
    if (v >= V) return;

    const float* vp = out + OFF_POSED + b * D3 + v * 3;
    float px = vp[0], py = vp[1], pz = vp[2];

    float4 w4[6];
    const float4* wp = (const float4*)(weights + v * NJ);
    #pragma unroll
    for (int q = 0; q < 6; q++) w4[q] = wp[q];
    const float* w = (const float*)w4;

    float T[12];
    #pragma unroll
    for (int r = 0; r < 12; r++) T[r] = 0.f;
    #pragma unroll
    for (int j = 0; j < NJ; j++) {
        float wj = w[j];
        #pragma unroll
        for (int r = 0; r < 12; r++) T[r] = fmaf(wj, Gs[j*12 + r], T[r]);
    }

    float ox = T[0]*px + T[1]*py + T[2]*pz  + T[3]  + tr[0];
    float oy = T[4]*px + T[5]*py + T[6]*pz  + T[7]  + tr[1];
    float oz = T[8]*px + T[9]*py + T[10]*pz + T[11] + tr[2];

    float* o = out + OFF_V + b * D3 + v * 3;
    o[0] = ox; o[1] = oy; o[2] = oz;
}

// ---------------- launch ----------------
extern "C" void kernel_launch(void* const* d_in, const int* in_sizes, int n_in,
                              void* d_out, int out_size) {
    const float* pose       = (const float*)d_in[0];
    const float* betas      = (const float*)d_in[1];
    const float* trans      = (const float*)d_in[2];
    const float* v_template = (const float*)d_in[3];
    const float* shapedirs  = (const float*)d_in[4];
    const float* posedirs   = (const float*)d_in[5];
    const float* Jr         = (const float*)d_in[6];
    const float* weights    = (const float*)d_in[7];
    float* out = (float*)d_out;

    const int dyn_smem = 2 * 64 * KF * (int)sizeof(float);   // 55296 B
    cudaFuncSetAttribute(k_gemm, cudaFuncAttributeMaxDynamicSharedMemorySize, dyn_smem);

    k_dirs<<<(D3PAD * KF + 255) / 256, 256>>>(shapedirs, posedirs);
    k_rot<<<(B * NJ + 127) / 128, 128>>>(pose);
    k_feat<<<(B * KF + 255) / 256, 256>>>(betas);

    dim3 g1((D3 + 63) / 64, B / 64);   // (323, 8)
    dim3 b1(16, 16);
    k_gemm<<<g1, b1, dyn_smem>>>(v_template, out);

    k_joints<<<B, 256>>>(out, Jr);
    k_chain<<<(B + 63) / 64, 64>>>(trans, out);

    dim3 g4((V + 255) / 256, B);
    k_skin<<<g4, 256>>>(weights, trans, out);
}